// round 12
// baseline (speedup 1.0000x reference)
#include <cuda_runtime.h>
#include <cuda_fp16.h>
#include <math.h>
#include <stdint.h>

// ---------------- problem constants ----------------
#define B_   2
#define N_   4096
#define D_   1024
#define H_   16
#define DH_  64
#define R_   64
#define L_   6
#define FF_  4096
#define INNER_ 1024
#define M_   (B_*N_)        // 8192 rows
#define EPS_ 1e-5f
#define STAB_ 1e-6f

// ---------------- scratch (static device globals; allowed) ----------------
__device__ __align__(16) __half g_qkv[M_ * 3 * INNER_];    // [phi_q | phi_k | v], half
__device__ __align__(16) __half g_ff1[M_ * FF_];
__device__ __align__(16) __half g_attnout[M_ * INNER_];
__device__ __align__(16) __half g_ln[M_ * D_];
__device__ __align__(16) float  g_kvpart[B_*H_*16*R_*DH_];
__device__ __align__(16) float  g_kspart[B_*H_*16*R_];
__device__ __align__(16) float  g_kv[B_*H_*R_*DH_];
__device__ __align__(16) float  g_ksum[B_*H_*R_];
// fp16 weights: g_Wqkvp holds combined [Wphi_q | Wphi_k | Wv] rows
__device__ __align__(16) __half g_Wqkvp[L_*3*INNER_*D_];
__device__ __align__(16) __half g_Woutp[L_*D_*INNER_];
__device__ __align__(16) __half g_W1p  [L_*FF_*D_];
__device__ __align__(16) __half g_W2p  [L_*D_*FF_];

// ---------------- helpers ----------------
__device__ __forceinline__ uint32_t smem_u32(const void* p) {
    uint32_t a;
    asm("{ .reg .u64 t; cvta.to.shared.u64 t, %1; cvt.u32.u64 %0, t; }" : "=r"(a) : "l"(p));
    return a;
}
__device__ __forceinline__ void cp16(uint32_t s, const void* g) {
    asm volatile("cp.async.cg.shared.global [%0], [%1], 16;\n" :: "r"(s), "l"(g));
}
#define LDSM_X4(r, addr) \
    asm volatile("ldmatrix.sync.aligned.m8n8.x4.shared.b16 {%0,%1,%2,%3}, [%4];" \
        : "=r"((r)[0]), "=r"((r)[1]), "=r"((r)[2]), "=r"((r)[3]) : "r"(addr))

// ---------------- FP16 tensor-core GEMM, 128x128 tile, k-chunk 32 -----------
// C[M,Nc] = A[M,K] @ Bw[Nc,K]^T  (+ epilogue)
// EPI: 0=none, 1=relu for col<relu_lim, 2=bias+GELU, 3=bias+residual(fp32).
// OUTH: write half vs float.
#define KC    32
#define RSTR  40
#define STAGEB (128 * RSTR * 2)

template<int EPI, bool OUTH>
__global__ __launch_bounds__(256) void gemm_fp16(
    const __half* __restrict__ A, const __half* __restrict__ Bw,
    void* __restrict__ Cv, int M, int Nc, int K,
    const float* __restrict__ bias, const float* __restrict__ resid, int relu_lim)
{
    __shared__ __align__(16) __half sh[2][2][128 * RSTR];
    const uint32_t sbase = smem_u32(&sh[0][0][0]);

    const int tid  = threadIdx.x;
    const int bm0  = blockIdx.y * 128;
    const int bn0  = blockIdx.x * 128;
    const int warp = tid >> 5;
    const int lane = tid & 31;
    const int wm   = warp >> 2;
    const int wn   = warp & 3;
    const int g8   = lane >> 2;
    const int qid  = lane & 3;

    float c[4][4][4];
    #pragma unroll
    for (int mi = 0; mi < 4; mi++)
        #pragma unroll
        for (int ni = 0; ni < 4; ni++)
            #pragma unroll
            for (int j = 0; j < 4; j++) c[mi][ni][j] = 0.0f;

    const int nIter = K / KC;

    auto load_stage = [&](int it, int buf) {
        const int k0 = it * KC;
        uint32_t sA = sbase + buf * 2 * STAGEB;
        uint32_t sB = sA + STAGEB;
        #pragma unroll
        for (int i = 0; i < 2; i++) {
            int f = i * 256 + tid;
            int row = f >> 2, seg = f & 3;
            cp16(sA + (row * RSTR + seg * 8) * 2,
                 &A[(size_t)(bm0 + row) * K + k0 + seg * 8]);
        }
        #pragma unroll
        for (int i = 0; i < 2; i++) {
            int f = i * 256 + tid;
            int row = f >> 2, seg = f & 3;
            cp16(sB + (row * RSTR + seg * 8) * 2,
                 &Bw[(size_t)(bn0 + row) * K + k0 + seg * 8]);
        }
        asm volatile("cp.async.commit_group;\n" ::: "memory");
    };

    load_stage(0, 0);

    for (int it = 0; it < nIter; it++) {
        int buf = it & 1;
        if (it + 1 < nIter) {
            load_stage(it + 1, buf ^ 1);
            asm volatile("cp.async.wait_group 1;\n" ::: "memory");
        } else {
            asm volatile("cp.async.wait_group 0;\n" ::: "memory");
        }
        __syncthreads();

        uint32_t sA = sbase + buf * 2 * STAGEB;
        uint32_t sB = sA + STAGEB;

        #pragma unroll
        for (int ks = 0; ks < KC; ks += 16) {
            uint32_t af[4][4];
            #pragma unroll
            for (int mi = 0; mi < 4; mi++) {
                int m0 = wm * 64 + mi * 16;
                uint32_t addr = sA + (((m0 + (lane & 15)) * RSTR) + ks + ((lane >> 4) << 3)) * 2;
                LDSM_X4(af[mi], addr);
            }
            uint32_t bf[2][4];
            #pragma unroll
            for (int nb = 0; nb < 2; nb++) {
                int n0 = wn * 32 + nb * 16;
                uint32_t addr = sB + (((n0 + (lane & 7) + ((lane >> 4) << 3)) * RSTR)
                                      + ks + (((lane >> 3) & 1) << 3)) * 2;
                LDSM_X4(bf[nb], addr);
            }
            #pragma unroll
            for (int mi = 0; mi < 4; mi++)
                #pragma unroll
                for (int ni = 0; ni < 4; ni++) {
                    uint32_t b0 = bf[ni >> 1][(ni & 1) * 2];
                    uint32_t b1 = bf[ni >> 1][(ni & 1) * 2 + 1];
                    asm volatile(
                        "mma.sync.aligned.m16n8k16.row.col.f32.f16.f16.f32 "
                        "{%0,%1,%2,%3}, {%4,%5,%6,%7}, {%8,%9}, {%0,%1,%2,%3};\n"
                        : "+f"(c[mi][ni][0]), "+f"(c[mi][ni][1]),
                          "+f"(c[mi][ni][2]), "+f"(c[mi][ni][3])
                        : "r"(af[mi][0]), "r"(af[mi][1]), "r"(af[mi][2]), "r"(af[mi][3]),
                          "r"(b0), "r"(b1));
                }
        }
        __syncthreads();
    }

    // ---- epilogue ----
    #pragma unroll
    for (int mi = 0; mi < 4; mi++) {
        int row0 = bm0 + wm * 64 + mi * 16 + g8;
        int row1 = row0 + 8;
        #pragma unroll
        for (int ni = 0; ni < 4; ni++) {
            int col = bn0 + wn * 32 + ni * 8 + qid * 2;
            float o0 = c[mi][ni][0], o1 = c[mi][ni][1];
            float o2 = c[mi][ni][2], o3 = c[mi][ni][3];
            if (EPI == 1) {
                if (col < relu_lim) {
                    o0 = fmaxf(o0, 0.0f); o1 = fmaxf(o1, 0.0f);
                    o2 = fmaxf(o2, 0.0f); o3 = fmaxf(o3, 0.0f);
                }
            }
            if (EPI >= 2) {
                float b0 = bias[col], b1 = bias[col + 1];
                o0 += b0; o1 += b1; o2 += b0; o3 += b1;
            }
            if (EPI == 2) {
                o0 = 0.5f * o0 * (1.0f + erff(o0 * 0.70710678118654752f));
                o1 = 0.5f * o1 * (1.0f + erff(o1 * 0.70710678118654752f));
                o2 = 0.5f * o2 * (1.0f + erff(o2 * 0.70710678118654752f));
                o3 = 0.5f * o3 * (1.0f + erff(o3 * 0.70710678118654752f));
            }
            if (EPI == 3) {
                float2 r0 = *(const float2*)&resid[(size_t)row0 * Nc + col];
                float2 r1 = *(const float2*)&resid[(size_t)row1 * Nc + col];
                o0 += r0.x; o1 += r0.y; o2 += r1.x; o3 += r1.y;
            }
            if (OUTH) {
                __half* C = (__half*)Cv;
                *(__half2*)&C[(size_t)row0 * Nc + col] = __floats2half2_rn(o0, o1);
                *(__half2*)&C[(size_t)row1 * Nc + col] = __floats2half2_rn(o2, o3);
            } else {
                float* C = (float*)Cv;
                *(float2*)&C[(size_t)row0 * Nc + col] = make_float2(o0, o1);
                *(float2*)&C[(size_t)row1 * Nc + col] = make_float2(o2, o3);
            }
        }
    }
}

// ---------------- weight convert: fp32 -> fp16 ----------------
__global__ __launch_bounds__(256) void wconv_kernel(
    const float* __restrict__ in, __half* __restrict__ out, int n4)
{
    int i = blockIdx.x * 256 + threadIdx.x;
    if (i >= n4) return;
    float4 v = *(const float4*)&in[(size_t)i * 4];
    *(__half2*)&out[(size_t)i * 4]     = __floats2half2_rn(v.x, v.y);
    *(__half2*)&out[(size_t)i * 4 + 2] = __floats2half2_rn(v.z, v.w);
}

// ---------------- combined phi weights: Wphi[c,(h,r)] = sum_d W[(h,d),c]*rf[h,d,r]
// one block per (l, qk, h); output rows (qk*INNER + h*R + r), fp16
__global__ __launch_bounds__(256) void wcomb_kernel(
    const float* __restrict__ Wqkv, const float* __restrict__ rf,
    __half* __restrict__ out)
{
    __shared__ float rfs[64 * 64];     // [d][r]
    __shared__ float wt[64][64];       // [d][c-tile]
    int blk = blockIdx.x;              // 0..191
    int l = blk >> 5, rest = blk & 31;
    int qk = rest >> 4, h = rest & 15;
    int tid = threadIdx.x;

    const float* W   = Wqkv + ((size_t)l * 3 * INNER_ + qk * INNER_ + h * DH_) * D_;
    const float* rfh = rf + ((size_t)(l * H_ + h)) * DH_ * R_;
    __half* o = out + (size_t)l * 3 * INNER_ * D_ + (size_t)(qk * INNER_ + h * R_) * D_;

    #pragma unroll
    for (int i = 0; i < 16; i++) rfs[tid + i * 256] = rfh[tid + i * 256];
    __syncthreads();

    int r  = tid >> 2;
    int j0 = (tid & 3) << 4;
    for (int ct = 0; ct < 16; ct++) {
        #pragma unroll
        for (int i = 0; i < 16; i++) {
            int f = tid + i * 256;
            int d = f >> 6, cc = f & 63;
            wt[d][cc] = W[(size_t)d * D_ + ct * 64 + cc];
        }
        __syncthreads();
        float acc[16];
        #pragma unroll
        for (int j = 0; j < 16; j++) acc[j] = 0.0f;
        for (int d = 0; d < 64; d++) {
            float p = rfs[d * 64 + r];
            #pragma unroll
            for (int j = 0; j < 16; j++) acc[j] = fmaf(p, wt[d][j0 + j], acc[j]);
        }
        #pragma unroll
        for (int j = 0; j < 16; j += 2)
            *(__half2*)&o[(size_t)r * D_ + ct * 64 + j0 + j] =
                __floats2half2_rn(acc[j], acc[j + 1]);
        __syncthreads();
    }
}

// ---------------- embedding ----------------
__global__ __launch_bounds__(256) void embed_kernel(
    const int* __restrict__ tokens, const float* __restrict__ te,
    const float* __restrict__ pe, float* __restrict__ x)
{
    int row = blockIdx.x;
    int tid = threadIdx.x;
    int n = row & (N_ - 1);
    int tok = tokens[row];
    float4 a = *(const float4*)&te[(size_t)tok * D_ + tid * 4];
    float4 p = *(const float4*)&pe[(size_t)n * D_ + tid * 4];
    a.x += p.x; a.y += p.y; a.z += p.z; a.w += p.w;
    *(float4*)&x[(size_t)row * D_ + tid * 4] = a;
}

// ---------------- fused LayerNorm (stats + apply -> fp16) -------------------
__global__ __launch_bounds__(256) void ln_kernel(
    const float* __restrict__ x, const float* __restrict__ lng,
    const float* __restrict__ lnb, __half* __restrict__ h)
{
    __shared__ float red[256];
    int row = blockIdx.x, tid = threadIdx.x;
    float4 v = *(const float4*)&x[(size_t)row * D_ + tid * 4];
    red[tid] = v.x + v.y + v.z + v.w; __syncthreads();
    #pragma unroll
    for (int o = 128; o > 0; o >>= 1) { if (tid < o) red[tid] += red[tid + o]; __syncthreads(); }
    float mu = red[0] * (1.0f / D_);
    __syncthreads();
    float dx = v.x - mu, dy = v.y - mu, dz = v.z - mu, dw = v.w - mu;
    red[tid] = dx*dx + dy*dy + dz*dz + dw*dw; __syncthreads();
    #pragma unroll
    for (int o = 128; o > 0; o >>= 1) { if (tid < o) red[tid] += red[tid + o]; __syncthreads(); }
    float rs = rsqrtf(red[0] * (1.0f / D_) + EPS_);
    float4 gg = *(const float4*)&lng[tid * 4];
    float4 bb = *(const float4*)&lnb[tid * 4];
    __half* hr = h + (size_t)row * D_ + tid * 4;
    *(__half2*)&hr[0] = __floats2half2_rn(dx * rs * gg.x + bb.x, dy * rs * gg.y + bb.y);
    *(__half2*)&hr[2] = __floats2half2_rn(dz * rs * gg.z + bb.z, dw * rs * gg.w + bb.w);
}

// ---------------- kv-sum: kv[r,d] = sum_n phi_k[n,r] * v[n,d] ---------------
// phi_k, v read directly from fp16 qkv buffer (relu already applied).
__global__ __launch_bounds__(256) void kvsum_kernel(
    const __half* __restrict__ qkvh,
    float* __restrict__ kvpart, float* __restrict__ kspart)
{
    __shared__ float phism[16][64];
    __shared__ float vsm[16][64];
    int tid = threadIdx.x;
    int bh = blockIdx.x;
    int b = bh >> 4, h = bh & 15;
    int chunk = blockIdx.y;

    int my_r  = tid >> 2;
    int my_d0 = (tid & 3) << 4;
    int r0    = (tid & 3) << 2;        // 4 rows of ksum work per thread
    float acc[16];
    #pragma unroll
    for (int j = 0; j < 16; j++) acc[j] = 0.0f;
    float kslocal = 0.0f;
    int nbase = chunk * 256;

    for (int g = 0; g < 16; g++) {
        #pragma unroll
        for (int i = 0; i < 2; i++) {
            int f = tid + i * 256;
            int row = f >> 5, c2 = (f & 31) << 1;
            int n = nbase + g * 16 + row;
            size_t base = ((size_t)(b * N_ + n)) * (3 * INNER_) + h * DH_ + c2;
            float2 pf = __half22float2(*(const __half2*)&qkvh[base + INNER_]);
            float2 vf = __half22float2(*(const __half2*)&qkvh[base + 2 * INNER_]);
            phism[row][c2] = pf.x; phism[row][c2 + 1] = pf.y;
            vsm[row][c2]   = vf.x; vsm[row][c2 + 1]   = vf.y;
        }
        __syncthreads();
        #pragma unroll
        for (int rr = 0; rr < 16; rr++) {
            float p = phism[rr][my_r];
            float4 v0 = *(const float4*)&vsm[rr][my_d0];
            float4 v1 = *(const float4*)&vsm[rr][my_d0 + 4];
            float4 v2 = *(const float4*)&vsm[rr][my_d0 + 8];
            float4 v3 = *(const float4*)&vsm[rr][my_d0 + 12];
            acc[0]  = fmaf(p, v0.x, acc[0]);  acc[1]  = fmaf(p, v0.y, acc[1]);
            acc[2]  = fmaf(p, v0.z, acc[2]);  acc[3]  = fmaf(p, v0.w, acc[3]);
            acc[4]  = fmaf(p, v1.x, acc[4]);  acc[5]  = fmaf(p, v1.y, acc[5]);
            acc[6]  = fmaf(p, v1.z, acc[6]);  acc[7]  = fmaf(p, v1.w, acc[7]);
            acc[8]  = fmaf(p, v2.x, acc[8]);  acc[9]  = fmaf(p, v2.y, acc[9]);
            acc[10] = fmaf(p, v2.z, acc[10]); acc[11] = fmaf(p, v2.w, acc[11]);
            acc[12] = fmaf(p, v3.x, acc[12]); acc[13] = fmaf(p, v3.y, acc[13]);
            acc[14] = fmaf(p, v3.z, acc[14]); acc[15] = fmaf(p, v3.w, acc[15]);
        }
        kslocal += phism[r0][my_r] + phism[r0 + 1][my_r]
                 + phism[r0 + 2][my_r] + phism[r0 + 3][my_r];
        __syncthreads();
    }

    float* kvp = kvpart + ((size_t)(bh * 16 + chunk)) * (R_ * DH_);
    #pragma unroll
    for (int j = 0; j < 16; j++) kvp[my_r * 64 + my_d0 + j] = acc[j];

    // reduce ksum across the 4 threads sharing my_r (adjacent lanes)
    kslocal += __shfl_xor_sync(0xffffffff, kslocal, 1);
    kslocal += __shfl_xor_sync(0xffffffff, kslocal, 2);
    if ((tid & 3) == 0)
        kspart[(bh * 16 + chunk) * R_ + my_r] = kslocal;
}

__global__ __launch_bounds__(256) void kvreduce_kernel(
    const float* __restrict__ kvpart, const float* __restrict__ kspart,
    float* __restrict__ kv, float* __restrict__ ks)
{
    int bh = blockIdx.x, tid = threadIdx.x;
    for (int i = tid; i < R_ * DH_; i += 256) {
        float s = 0.0f;
        #pragma unroll
        for (int c = 0; c < 16; c++)
            s += kvpart[((size_t)(bh * 16 + c)) * (R_ * DH_) + i];
        kv[(size_t)bh * (R_ * DH_) + i] = s;
    }
    if (tid < 64) {
        float s = 0.0f;
        #pragma unroll
        for (int c = 0; c < 16; c++) s += kspart[(bh * 16 + c) * R_ + tid];
        ks[bh * R_ + tid] = s;
    }
}

// ---------------- attention out: out = (phi_q @ kv) / (phi_q . ksum) --------
#define PSTR 66   // phi smem row stride in halves (conflict-free)
__global__ __launch_bounds__(256) void attnout_kernel(
    const __half* __restrict__ qkvh,
    const float* __restrict__ kv, const float* __restrict__ ksum,
    __half* __restrict__ out)
{
    __shared__ __half phis[128 * PSTR];
    __shared__ float kvsm[64 * 68];    // [r][d] stride 68
    __shared__ float kss[64];
    __shared__ float nzs[128];
    int tid = threadIdx.x;
    int bh = blockIdx.x;
    int b = bh >> 4, h = bh & 15;
    int nbase = blockIdx.y * 128;

    const float* kvg = kv + (size_t)bh * (R_ * DH_);
    for (int i = tid; i < R_ * DH_; i += 256) {
        int r = i >> 6, d = i & 63;
        kvsm[r * 68 + d] = kvg[i];
    }
    if (tid < 64) kss[tid] = ksum[bh * R_ + tid];

    // load phi_q tile [128][64] (fp16, relu'd already)
    #pragma unroll
    for (int i = 0; i < 16; i++) {
        int f = tid + i * 256;             // 0..4095 half2 slots
        int row = f >> 5, c2 = (f & 31) << 1;
        int n = nbase + row;
        *(__half2*)&phis[row * PSTR + c2] =
            *(const __half2*)&qkvh[((size_t)(b * N_ + n)) * (3 * INNER_) + h * DH_ + c2];
    }
    __syncthreads();

    // normalizers
    if (tid < 128) {
        float z = 0.0f;
        #pragma unroll
        for (int rc = 0; rc < 32; rc++) {
            float2 pf = __half22float2(*(const __half2*)&phis[tid * PSTR + rc * 2]);
            z = fmaf(pf.x, kss[rc * 2], z);
            z = fmaf(pf.y, kss[rc * 2 + 1], z);
        }
        nzs[tid] = z;
    }
    __syncthreads();

    int d0 = (tid & 3) << 4;
    int nr = tid >> 2;                     // 0..63
    #pragma unroll
    for (int hf = 0; hf < 2; hf++) {
        int n = hf * 64 + nr;
        float acc[16];
        #pragma unroll
        for (int j = 0; j < 16; j++) acc[j] = 0.0f;
        #pragma unroll
        for (int r = 0; r < 64; r += 2) {
            float2 pf = __half22float2(*(const __half2*)&phis[n * PSTR + r]);
            const float* k0 = &kvsm[r * 68 + d0];
            const float* k1 = &kvsm[(r + 1) * 68 + d0];
            float4 a0 = *(const float4*)&k0[0],  a1 = *(const float4*)&k0[4];
            float4 a2 = *(const float4*)&k0[8],  a3 = *(const float4*)&k0[12];
            float4 b0 = *(const float4*)&k1[0],  b1 = *(const float4*)&k1[4];
            float4 b2 = *(const float4*)&k1[8],  b3 = *(const float4*)&k1[12];
            acc[0]  = fmaf(pf.x, a0.x, fmaf(pf.y, b0.x, acc[0]));
            acc[1]  = fmaf(pf.x, a0.y, fmaf(pf.y, b0.y, acc[1]));
            acc[2]  = fmaf(pf.x, a0.z, fmaf(pf.y, b0.z, acc[2]));
            acc[3]  = fmaf(pf.x, a0.w, fmaf(pf.y, b0.w, acc[3]));
            acc[4]  = fmaf(pf.x, a1.x, fmaf(pf.y, b1.x, acc[4]));
            acc[5]  = fmaf(pf.x, a1.y, fmaf(pf.y, b1.y, acc[5]));
            acc[6]  = fmaf(pf.x, a1.z, fmaf(pf.y, b1.z, acc[6]));
            acc[7]  = fmaf(pf.x, a1.w, fmaf(pf.y, b1.w, acc[7]));
            acc[8]  = fmaf(pf.x, a2.x, fmaf(pf.y, b2.x, acc[8]));
            acc[9]  = fmaf(pf.x, a2.y, fmaf(pf.y, b2.y, acc[9]));
            acc[10] = fmaf(pf.x, a2.z, fmaf(pf.y, b2.z, acc[10]));
            acc[11] = fmaf(pf.x, a2.w, fmaf(pf.y, b2.w, acc[11]));
            acc[12] = fmaf(pf.x, a3.x, fmaf(pf.y, b3.x, acc[12]));
            acc[13] = fmaf(pf.x, a3.y, fmaf(pf.y, b3.y, acc[13]));
            acc[14] = fmaf(pf.x, a3.z, fmaf(pf.y, b3.z, acc[14]));
            acc[15] = fmaf(pf.x, a3.w, fmaf(pf.y, b3.w, acc[15]));
        }
        float inv = 1.0f / (nzs[n] + STAB_);
        __half* op = out + ((size_t)(b * N_ + nbase + n)) * INNER_ + h * DH_ + d0;
        #pragma unroll
        for (int j = 0; j < 16; j += 2)
            *(__half2*)&op[j] = __floats2half2_rn(acc[j] * inv, acc[j + 1] * inv);
    }
}

// ---------------- host driver ----------------
extern "C" void kernel_launch(void* const* d_in, const int* in_sizes, int n_in,
                              void* d_out, int out_size)
{
    const int*   tokens  = (const int*)  d_in[0];
    const float* tok_emb = (const float*)d_in[1];
    const float* pos_emb = (const float*)d_in[2];
    const float* Wqkv    = (const float*)d_in[3];
    const float* Wout    = (const float*)d_in[4];
    const float* bout    = (const float*)d_in[5];
    const float* ln1g    = (const float*)d_in[6];
    const float* ln1b    = (const float*)d_in[7];
    const float* ln2g    = (const float*)d_in[8];
    const float* ln2b    = (const float*)d_in[9];
    const float* W1      = (const float*)d_in[10];
    const float* b1      = (const float*)d_in[11];
    const float* W2      = (const float*)d_in[12];
    const float* b2      = (const float*)d_in[13];
    const float* rf      = (const float*)d_in[14];
    float* x = (float*)d_out;

    float *kvpart, *kspart, *kv, *ksum;
    __half *qkv, *ff1, *attnout, *ln, *Wqkvp, *Woutp, *W1p, *W2p;
    cudaGetSymbolAddress((void**)&qkv,     g_qkv);
    cudaGetSymbolAddress((void**)&ff1,     g_ff1);
    cudaGetSymbolAddress((void**)&attnout, g_attnout);
    cudaGetSymbolAddress((void**)&ln,      g_ln);
    cudaGetSymbolAddress((void**)&kvpart,  g_kvpart);
    cudaGetSymbolAddress((void**)&kspart,  g_kspart);
    cudaGetSymbolAddress((void**)&kv,      g_kv);
    cudaGetSymbolAddress((void**)&ksum,    g_ksum);
    cudaGetSymbolAddress((void**)&Wqkvp,   g_Wqkvp);
    cudaGetSymbolAddress((void**)&Woutp,   g_Woutp);
    cudaGetSymbolAddress((void**)&W1p,     g_W1p);
    cudaGetSymbolAddress((void**)&W2p,     g_W2p);

    // weight prep: combined phi weights + fp16 conversions
    wcomb_kernel<<<L_ * 2 * H_, 256>>>(Wqkv, rf, Wqkvp);
    for (int l = 0; l < L_; l++) {
        int n4 = INNER_ * D_ / 4;
        wconv_kernel<<<(n4 + 255) / 256, 256>>>(
            Wqkv + (size_t)l * 3 * INNER_ * D_ + 2 * (size_t)INNER_ * D_,
            Wqkvp + (size_t)l * 3 * INNER_ * D_ + 2 * (size_t)INNER_ * D_, n4);
    }
    {
        int n4;
        n4 = L_*D_*INNER_ / 4; wconv_kernel<<<(n4+255)/256, 256>>>(Wout, Woutp, n4);
        n4 = L_*FF_*D_    / 4; wconv_kernel<<<(n4+255)/256, 256>>>(W1,   W1p,   n4);
        n4 = L_*D_*FF_    / 4; wconv_kernel<<<(n4+255)/256, 256>>>(W2,   W2p,   n4);
    }

    embed_kernel<<<M_, 256>>>(tokens, tok_emb, pos_emb, x);

    for (int l = 0; l < L_; l++) {
        const __half* Wqkv_l = Wqkvp + (size_t)l * 3 * INNER_ * D_;
        const __half* Wout_l = Woutp + (size_t)l * D_ * INNER_;
        const float* bout_l = bout + (size_t)l * D_;
        const float* ln1g_l = ln1g + (size_t)l * D_;
        const float* ln1b_l = ln1b + (size_t)l * D_;
        const float* ln2g_l = ln2g + (size_t)l * D_;
        const float* ln2b_l = ln2b + (size_t)l * D_;
        const __half* W1_l  = W1p  + (size_t)l * FF_ * D_;
        const float* b1_l   = b1   + (size_t)l * FF_;
        const __half* W2_l  = W2p  + (size_t)l * D_ * FF_;
        const float* b2_l   = b2   + (size_t)l * D_;

        // --- attention block ---
        ln_kernel<<<M_, 256>>>(x, ln1g_l, ln1b_l, ln);
        gemm_fp16<1, true><<<dim3(3 * INNER_ / 128, M_ / 128), 256>>>(
            ln, Wqkv_l, qkv, M_, 3 * INNER_, D_, nullptr, nullptr, 2 * INNER_);
        kvsum_kernel<<<dim3(B_ * H_, 16), 256>>>(qkv, kvpart, kspart);
        kvreduce_kernel<<<B_ * H_, 256>>>(kvpart, kspart, kv, ksum);
        attnout_kernel<<<dim3(B_ * H_, N_ / 128), 256>>>(qkv, kv, ksum, attnout);
        gemm_fp16<3, false><<<dim3(D_ / 128, M_ / 128), 256>>>(
            attnout, Wout_l, x, M_, D_, INNER_, bout_l, x, 0);

        // --- FFN block ---
        ln_kernel<<<M_, 256>>>(x, ln2g_l, ln2b_l, ln);
        gemm_fp16<2, true><<<dim3(FF_ / 128, M_ / 128), 256>>>(
            ln, W1_l, ff1, M_, FF_, D_, b1_l, nullptr, 0);
        gemm_fp16<3, false><<<dim3(D_ / 128, M_ / 128), 256>>>(
            ff1, W2_l, x, M_, D_, FF_, b2_l, x, 0);
    }
}

// round 13
// speedup vs baseline: 1.1585x; 1.1585x over previous
#include <cuda_runtime.h>
#include <cuda_fp16.h>
#include <math.h>
#include <stdint.h>

// ---------------- problem constants ----------------
#define B_   2
#define N_   4096
#define D_   1024
#define H_   16
#define DH_  64
#define R_   64
#define L_   6
#define FF_  4096
#define INNER_ 1024
#define M_   (B_*N_)        // 8192 rows
#define EPS_ 1e-5f
#define STAB_ 1e-6f
#define NCHUNK_ 32          // kv-sum chunks per (b,h)

// ---------------- scratch (static device globals; allowed) ----------------
__device__ __align__(16) float  g_qkv[M_ * 3 * INNER_];    // fp32 (attention reads)
__device__ __align__(16) __half g_ff1[M_ * FF_];           // half
__device__ __align__(16) __half g_attnout[M_ * INNER_];    // half
__device__ __align__(16) __half g_ln[M_ * D_];             // half
__device__ __align__(16) float  g_kvpart[B_*H_*NCHUNK_*R_*DH_];
__device__ __align__(16) float  g_kspart[B_*H_*NCHUNK_*R_];
__device__ __align__(16) float  g_kv[B_*H_*R_*DH_];
__device__ __align__(16) float  g_ksum[B_*H_*R_];
// fp16 weight copies (K-major)
__device__ __align__(16) __half g_Wqkvp[L_*3*INNER_*D_];
__device__ __align__(16) __half g_Woutp[L_*D_*INNER_];
__device__ __align__(16) __half g_W1p  [L_*FF_*D_];
__device__ __align__(16) __half g_W2p  [L_*D_*FF_];

// ---------------- helpers ----------------
__device__ __forceinline__ uint32_t smem_u32(const void* p) {
    uint32_t a;
    asm("{ .reg .u64 t; cvta.to.shared.u64 t, %1; cvt.u32.u64 %0, t; }" : "=r"(a) : "l"(p));
    return a;
}
__device__ __forceinline__ void cp16(uint32_t s, const void* g) {
    asm volatile("cp.async.cg.shared.global [%0], [%1], 16;\n" :: "r"(s), "l"(g));
}
#define LDSM_X4(r, addr) \
    asm volatile("ldmatrix.sync.aligned.m8n8.x4.shared.b16 {%0,%1,%2,%3}, [%4];" \
        : "=r"((r)[0]), "=r"((r)[1]), "=r"((r)[2]), "=r"((r)[3]) : "r"(addr))

// ---------------- FP16 tensor-core GEMM, 128x128 tile, k-chunk 32 -----------
// C[M,Nc] = A[M,K] @ Bw[Nc,K]^T  (+ epilogue)
// EPI: 0 = none, 2 = bias+GELU, 3 = bias+residual(fp32).
// OUTH: write half (next GEMM's A) vs float.
#define KC    32          // k-chunk in halves
#define RSTR  40          // row stride in halves (80B) -> conflict-free ldmatrix
#define STAGEB (128 * RSTR * 2)   // bytes per tile stage

template<int EPI, bool OUTH>
__global__ __launch_bounds__(256) void gemm_fp16(
    const __half* __restrict__ A, const __half* __restrict__ Bw,
    void* __restrict__ Cv, int M, int Nc, int K,
    const float* __restrict__ bias, const float* __restrict__ resid)
{
    __shared__ __align__(16) __half sh[2][2][128 * RSTR];
    const uint32_t sbase = smem_u32(&sh[0][0][0]);

    const int tid  = threadIdx.x;
    const int bm0  = blockIdx.y * 128;
    const int bn0  = blockIdx.x * 128;
    const int warp = tid >> 5;
    const int lane = tid & 31;
    const int wm   = warp >> 2;     // 0..1 -> 64-row slab
    const int wn   = warp & 3;      // 0..3 -> 32-col slab
    const int g8   = lane >> 2;     // 0..7 (c-frag row group)
    const int qid  = lane & 3;

    float c[4][4][4];
    #pragma unroll
    for (int mi = 0; mi < 4; mi++)
        #pragma unroll
        for (int ni = 0; ni < 4; ni++)
            #pragma unroll
            for (int j = 0; j < 4; j++) c[mi][ni][j] = 0.0f;

    const int nIter = K / KC;

    auto load_stage = [&](int it, int buf) {
        const int k0 = it * KC;
        uint32_t sA = sbase + buf * 2 * STAGEB;
        uint32_t sB = sA + STAGEB;
        #pragma unroll
        for (int i = 0; i < 2; i++) {
            int f = i * 256 + tid;          // 0..511
            int row = f >> 2, seg = f & 3;  // seg: 8-half (16B) segment
            cp16(sA + (row * RSTR + seg * 8) * 2,
                 &A[(size_t)(bm0 + row) * K + k0 + seg * 8]);
        }
        #pragma unroll
        for (int i = 0; i < 2; i++) {
            int f = i * 256 + tid;
            int row = f >> 2, seg = f & 3;
            cp16(sB + (row * RSTR + seg * 8) * 2,
                 &Bw[(size_t)(bn0 + row) * K + k0 + seg * 8]);
        }
        asm volatile("cp.async.commit_group;\n" ::: "memory");
    };

    load_stage(0, 0);

    for (int it = 0; it < nIter; it++) {
        int buf = it & 1;
        if (it + 1 < nIter) {
            load_stage(it + 1, buf ^ 1);
            asm volatile("cp.async.wait_group 1;\n" ::: "memory");
        } else {
            asm volatile("cp.async.wait_group 0;\n" ::: "memory");
        }
        __syncthreads();

        uint32_t sA = sbase + buf * 2 * STAGEB;
        uint32_t sB = sA + STAGEB;

        #pragma unroll
        for (int ks = 0; ks < KC; ks += 16) {
            uint32_t af[4][4];
            #pragma unroll
            for (int mi = 0; mi < 4; mi++) {
                int m0 = wm * 64 + mi * 16;
                uint32_t addr = sA + (((m0 + (lane & 15)) * RSTR) + ks + ((lane >> 4) << 3)) * 2;
                LDSM_X4(af[mi], addr);
            }
            uint32_t bf[2][4];
            #pragma unroll
            for (int nb = 0; nb < 2; nb++) {
                int n0 = wn * 32 + nb * 16;
                uint32_t addr = sB + (((n0 + (lane & 7) + ((lane >> 4) << 3)) * RSTR)
                                      + ks + (((lane >> 3) & 1) << 3)) * 2;
                LDSM_X4(bf[nb], addr);
            }
            #pragma unroll
            for (int mi = 0; mi < 4; mi++)
                #pragma unroll
                for (int ni = 0; ni < 4; ni++) {
                    uint32_t b0 = bf[ni >> 1][(ni & 1) * 2];
                    uint32_t b1 = bf[ni >> 1][(ni & 1) * 2 + 1];
                    asm volatile(
                        "mma.sync.aligned.m16n8k16.row.col.f32.f16.f16.f32 "
                        "{%0,%1,%2,%3}, {%4,%5,%6,%7}, {%8,%9}, {%0,%1,%2,%3};\n"
                        : "+f"(c[mi][ni][0]), "+f"(c[mi][ni][1]),
                          "+f"(c[mi][ni][2]), "+f"(c[mi][ni][3])
                        : "r"(af[mi][0]), "r"(af[mi][1]), "r"(af[mi][2]), "r"(af[mi][3]),
                          "r"(b0), "r"(b1));
                }
        }
        __syncthreads();
    }

    // ---- epilogue ----
    #pragma unroll
    for (int mi = 0; mi < 4; mi++) {
        int row0 = bm0 + wm * 64 + mi * 16 + g8;
        int row1 = row0 + 8;
        #pragma unroll
        for (int ni = 0; ni < 4; ni++) {
            int col = bn0 + wn * 32 + ni * 8 + qid * 2;
            float o0 = c[mi][ni][0], o1 = c[mi][ni][1];
            float o2 = c[mi][ni][2], o3 = c[mi][ni][3];
            if (EPI >= 1) {
                float b0 = bias[col], b1 = bias[col + 1];
                o0 += b0; o1 += b1; o2 += b0; o3 += b1;
            }
            if (EPI == 2) {
                o0 = 0.5f * o0 * (1.0f + erff(o0 * 0.70710678118654752f));
                o1 = 0.5f * o1 * (1.0f + erff(o1 * 0.70710678118654752f));
                o2 = 0.5f * o2 * (1.0f + erff(o2 * 0.70710678118654752f));
                o3 = 0.5f * o3 * (1.0f + erff(o3 * 0.70710678118654752f));
            }
            if (EPI == 3) {
                float2 r0 = *(const float2*)&resid[(size_t)row0 * Nc + col];
                float2 r1 = *(const float2*)&resid[(size_t)row1 * Nc + col];
                o0 += r0.x; o1 += r0.y; o2 += r1.x; o3 += r1.y;
            }
            if (OUTH) {
                __half* C = (__half*)Cv;
                *(__half2*)&C[(size_t)row0 * Nc + col] = __floats2half2_rn(o0, o1);
                *(__half2*)&C[(size_t)row1 * Nc + col] = __floats2half2_rn(o2, o3);
            } else {
                float* C = (float*)Cv;
                *(float2*)&C[(size_t)row0 * Nc + col] = make_float2(o0, o1);
                *(float2*)&C[(size_t)row1 * Nc + col] = make_float2(o2, o3);
            }
        }
    }
}

// ---------------- weight convert: fp32 -> fp16 ----------------
__global__ __launch_bounds__(256) void wconv_kernel(
    const float* __restrict__ in, __half* __restrict__ out, int n4)
{
    int i = blockIdx.x * 256 + threadIdx.x;
    if (i >= n4) return;
    float4 v = *(const float4*)&in[(size_t)i * 4];
    *(__half2*)&out[(size_t)i * 4]     = __floats2half2_rn(v.x, v.y);
    *(__half2*)&out[(size_t)i * 4 + 2] = __floats2half2_rn(v.z, v.w);
}

// ---------------- embedding ----------------
__global__ __launch_bounds__(256) void embed_kernel(
    const int* __restrict__ tokens, const float* __restrict__ te,
    const float* __restrict__ pe, float* __restrict__ x)
{
    int row = blockIdx.x;
    int tid = threadIdx.x;
    int n = row & (N_ - 1);
    int tok = tokens[row];
    float4 a = *(const float4*)&te[(size_t)tok * D_ + tid * 4];
    float4 p = *(const float4*)&pe[(size_t)n * D_ + tid * 4];
    a.x += p.x; a.y += p.y; a.z += p.z; a.w += p.w;
    *(float4*)&x[(size_t)row * D_ + tid * 4] = a;
}

// ---------------- fused LayerNorm (stats + apply -> fp16) -------------------
__global__ __launch_bounds__(256) void ln_kernel(
    const float* __restrict__ x, const float* __restrict__ lng,
    const float* __restrict__ lnb, __half* __restrict__ h)
{
    __shared__ float red[256];
    int row = blockIdx.x, tid = threadIdx.x;
    float4 v = *(const float4*)&x[(size_t)row * D_ + tid * 4];
    red[tid] = v.x + v.y + v.z + v.w; __syncthreads();
    #pragma unroll
    for (int o = 128; o > 0; o >>= 1) { if (tid < o) red[tid] += red[tid + o]; __syncthreads(); }
    float mu = red[0] * (1.0f / D_);
    __syncthreads();
    float dx = v.x - mu, dy = v.y - mu, dz = v.z - mu, dw = v.w - mu;
    red[tid] = dx*dx + dy*dy + dz*dz + dw*dw; __syncthreads();
    #pragma unroll
    for (int o = 128; o > 0; o >>= 1) { if (tid < o) red[tid] += red[tid + o]; __syncthreads(); }
    float rs = rsqrtf(red[0] * (1.0f / D_) + EPS_);
    float4 gg = *(const float4*)&lng[tid * 4];
    float4 bb = *(const float4*)&lnb[tid * 4];
    __half* hr = h + (size_t)row * D_ + tid * 4;
    *(__half2*)&hr[0] = __floats2half2_rn(dx * rs * gg.x + bb.x, dy * rs * gg.y + bb.y);
    *(__half2*)&hr[2] = __floats2half2_rn(dz * rs * gg.z + bb.z, dw * rs * gg.w + bb.w);
}

// ---------------- kv-sum (round-11 structure, 32 chunks of 128 rows) --------
__global__ __launch_bounds__(256) void kvsum_kernel(
    const float* __restrict__ qkv, const float* __restrict__ rf_l,
    float* __restrict__ kvpart, float* __restrict__ kspart)
{
    __shared__ float ksm[8][64];
    __shared__ float vsm[8][64];
    __shared__ float phism[8][64];
    int tid = threadIdx.x;
    int bh = blockIdx.x;
    int b = bh >> 4, h = bh & 15;
    int chunk = blockIdx.y;            // 0..31, 128 rows each

    int prow = tid >> 6, pr = tid & 63;
    const float* rfh = rf_l + h * (DH_ * R_);
    float rfr[64];
    #pragma unroll
    for (int d = 0; d < 64; d++) rfr[d] = rfh[d * 64 + pr];

    float acc[16];
    #pragma unroll
    for (int j = 0; j < 16; j++) acc[j] = 0.0f;
    int my_r  = tid >> 2;
    int my_d0 = (tid & 3) << 4;
    float kslocal = 0.0f;
    int nbase = chunk * 128;

    for (int gidx = 0; gidx < 16; gidx++) {
        int n0 = nbase + gidx * 8 + prow;
        size_t base0 = ((size_t)(b * N_ + n0)) * (3 * INNER_) + h * DH_;
        size_t base1 = base0 + (size_t)4 * (3 * INNER_);
        ksm[prow    ][pr] = qkv[base0 + INNER_ + pr];
        ksm[prow + 4][pr] = qkv[base1 + INNER_ + pr];
        vsm[prow    ][pr] = qkv[base0 + 2 * INNER_ + pr];
        vsm[prow + 4][pr] = qkv[base1 + 2 * INNER_ + pr];
        __syncthreads();
        float s0 = 0.0f, s1 = 0.0f;
        #pragma unroll
        for (int dc = 0; dc < 16; dc++) {
            float4 k0 = *(const float4*)&ksm[prow    ][dc * 4];
            float4 k1 = *(const float4*)&ksm[prow + 4][dc * 4];
            s0 = fmaf(k0.x, rfr[dc*4+0], s0); s0 = fmaf(k0.y, rfr[dc*4+1], s0);
            s0 = fmaf(k0.z, rfr[dc*4+2], s0); s0 = fmaf(k0.w, rfr[dc*4+3], s0);
            s1 = fmaf(k1.x, rfr[dc*4+0], s1); s1 = fmaf(k1.y, rfr[dc*4+1], s1);
            s1 = fmaf(k1.z, rfr[dc*4+2], s1); s1 = fmaf(k1.w, rfr[dc*4+3], s1);
        }
        s0 = fmaxf(s0, 0.0f); s1 = fmaxf(s1, 0.0f);
        phism[prow    ][pr] = s0;
        phism[prow + 4][pr] = s1;
        kslocal += s0 + s1;
        __syncthreads();
        #pragma unroll
        for (int rr = 0; rr < 8; rr++) {
            float p = phism[rr][my_r];
            float4 v0 = *(const float4*)&vsm[rr][my_d0];
            float4 v1 = *(const float4*)&vsm[rr][my_d0 + 4];
            float4 v2 = *(const float4*)&vsm[rr][my_d0 + 8];
            float4 v3 = *(const float4*)&vsm[rr][my_d0 + 12];
            acc[0]  = fmaf(p, v0.x, acc[0]);  acc[1]  = fmaf(p, v0.y, acc[1]);
            acc[2]  = fmaf(p, v0.z, acc[2]);  acc[3]  = fmaf(p, v0.w, acc[3]);
            acc[4]  = fmaf(p, v1.x, acc[4]);  acc[5]  = fmaf(p, v1.y, acc[5]);
            acc[6]  = fmaf(p, v1.z, acc[6]);  acc[7]  = fmaf(p, v1.w, acc[7]);
            acc[8]  = fmaf(p, v2.x, acc[8]);  acc[9]  = fmaf(p, v2.y, acc[9]);
            acc[10] = fmaf(p, v2.z, acc[10]); acc[11] = fmaf(p, v2.w, acc[11]);
            acc[12] = fmaf(p, v3.x, acc[12]); acc[13] = fmaf(p, v3.y, acc[13]);
            acc[14] = fmaf(p, v3.z, acc[14]); acc[15] = fmaf(p, v3.w, acc[15]);
        }
        __syncthreads();
    }

    float* kvp = kvpart + ((size_t)(bh * NCHUNK_ + chunk)) * (R_ * DH_);
    #pragma unroll
    for (int j = 0; j < 16; j++) kvp[my_r * 64 + my_d0 + j] = acc[j];

    phism[prow][pr] = kslocal;
    __syncthreads();
    if (tid < 64) {
        float s = phism[0][tid] + phism[1][tid] + phism[2][tid] + phism[3][tid];
        kspart[(bh * NCHUNK_ + chunk) * R_ + tid] = s;
    }
}

__global__ __launch_bounds__(256) void kvreduce_kernel(
    const float* __restrict__ kvpart, const float* __restrict__ kspart,
    float* __restrict__ kv, float* __restrict__ ks)
{
    int bh = blockIdx.x, tid = threadIdx.x;
    for (int i = tid; i < R_ * DH_; i += 256) {
        float s = 0.0f;
        #pragma unroll
        for (int c = 0; c < NCHUNK_; c++)
            s += kvpart[((size_t)(bh * NCHUNK_ + c)) * (R_ * DH_) + i];
        kv[(size_t)bh * (R_ * DH_) + i] = s;
    }
    if (tid < 64) {
        float s = 0.0f;
        #pragma unroll
        for (int c = 0; c < NCHUNK_; c++) s += kspart[(bh * NCHUNK_ + c) * R_ + tid];
        ks[bh * R_ + tid] = s;
    }
}

// ---------------- attention out (writes fp16) ----------------
__global__ __launch_bounds__(256) void attnout_kernel(
    const float* __restrict__ qkv, const float* __restrict__ rf_l,
    const float* __restrict__ kv, const float* __restrict__ ksum,
    __half* __restrict__ out)
{
    __shared__ float kvT[64 * 68];
    __shared__ float kssm[R_];
    __shared__ float qsm[8][64];
    __shared__ float phism[8][64];
    int tid = threadIdx.x;
    int bh = blockIdx.x;
    int b = bh >> 4, h = bh & 15;
    int tile = blockIdx.y;

    int prow = tid >> 6, pr = tid & 63;
    const float* rfh = rf_l + h * (DH_ * R_);
    float rfr[64];
    #pragma unroll
    for (int d = 0; d < 64; d++) rfr[d] = rfh[d * 64 + pr];

    const float* kvg = kv + (size_t)bh * (R_ * DH_);
    for (int i = tid; i < R_ * DH_; i += 256) {
        int r = i >> 6, d = i & 63;
        kvT[d * 68 + r] = kvg[i];
    }
    if (tid < 64) kssm[tid] = ksum[bh * R_ + tid];
    __syncthreads();

    int nbase = tile * 128;
    for (int gidx = 0; gidx < 16; gidx++) {
        int n0 = nbase + gidx * 8 + prow;
        size_t base0 = ((size_t)(b * N_ + n0)) * (3 * INNER_) + h * DH_;
        size_t base1 = base0 + (size_t)4 * (3 * INNER_);
        qsm[prow    ][pr] = qkv[base0 + pr];
        qsm[prow + 4][pr] = qkv[base1 + pr];
        __syncthreads();
        float s0 = 0.0f, s1 = 0.0f;
        #pragma unroll
        for (int dc = 0; dc < 16; dc++) {
            float4 q0 = *(const float4*)&qsm[prow    ][dc * 4];
            float4 q1 = *(const float4*)&qsm[prow + 4][dc * 4];
            s0 = fmaf(q0.x, rfr[dc*4+0], s0); s0 = fmaf(q0.y, rfr[dc*4+1], s0);
            s0 = fmaf(q0.z, rfr[dc*4+2], s0); s0 = fmaf(q0.w, rfr[dc*4+3], s0);
            s1 = fmaf(q1.x, rfr[dc*4+0], s1); s1 = fmaf(q1.y, rfr[dc*4+1], s1);
            s1 = fmaf(q1.z, rfr[dc*4+2], s1); s1 = fmaf(q1.w, rfr[dc*4+3], s1);
        }
        phism[prow    ][pr] = fmaxf(s0, 0.0f);
        phism[prow + 4][pr] = fmaxf(s1, 0.0f);
        __syncthreads();
        float a0 = 0.0f, a1 = 0.0f, z0 = 0.0f, z1 = 0.0f;
        #pragma unroll
        for (int rc = 0; rc < 16; rc++) {
            float4 p0 = *(const float4*)&phism[prow    ][rc * 4];
            float4 p1 = *(const float4*)&phism[prow + 4][rc * 4];
            float4 kk = *(const float4*)&kvT[pr * 68 + rc * 4];
            float4 ss = *(const float4*)&kssm[rc * 4];
            a0 = fmaf(p0.x, kk.x, a0); a0 = fmaf(p0.y, kk.y, a0);
            a0 = fmaf(p0.z, kk.z, a0); a0 = fmaf(p0.w, kk.w, a0);
            z0 = fmaf(p0.x, ss.x, z0); z0 = fmaf(p0.y, ss.y, z0);
            z0 = fmaf(p0.z, ss.z, z0); z0 = fmaf(p0.w, ss.w, z0);
            a1 = fmaf(p1.x, kk.x, a1); a1 = fmaf(p1.y, kk.y, a1);
            a1 = fmaf(p1.z, kk.z, a1); a1 = fmaf(p1.w, kk.w, a1);
            z1 = fmaf(p1.x, ss.x, z1); z1 = fmaf(p1.y, ss.y, z1);
            z1 = fmaf(p1.z, ss.z, z1); z1 = fmaf(p1.w, ss.w, z1);
        }
        out[((size_t)(b * N_ + n0    )) * INNER_ + h * DH_ + pr] = __float2half_rn(a0 / (z0 + STAB_));
        out[((size_t)(b * N_ + n0 + 4)) * INNER_ + h * DH_ + pr] = __float2half_rn(a1 / (z1 + STAB_));
        __syncthreads();
    }
}

// ---------------- host driver ----------------
extern "C" void kernel_launch(void* const* d_in, const int* in_sizes, int n_in,
                              void* d_out, int out_size)
{
    const int*   tokens  = (const int*)  d_in[0];
    const float* tok_emb = (const float*)d_in[1];
    const float* pos_emb = (const float*)d_in[2];
    const float* Wqkv    = (const float*)d_in[3];
    const float* Wout    = (const float*)d_in[4];
    const float* bout    = (const float*)d_in[5];
    const float* ln1g    = (const float*)d_in[6];
    const float* ln1b    = (const float*)d_in[7];
    const float* ln2g    = (const float*)d_in[8];
    const float* ln2b    = (const float*)d_in[9];
    const float* W1      = (const float*)d_in[10];
    const float* b1      = (const float*)d_in[11];
    const float* W2      = (const float*)d_in[12];
    const float* b2      = (const float*)d_in[13];
    const float* rf      = (const float*)d_in[14];
    float* x = (float*)d_out;

    float *qkv, *kvpart, *kspart, *kv, *ksum;
    __half *ff1, *attnout, *ln, *Wqkvp, *Woutp, *W1p, *W2p;
    cudaGetSymbolAddress((void**)&qkv,     g_qkv);
    cudaGetSymbolAddress((void**)&ff1,     g_ff1);
    cudaGetSymbolAddress((void**)&attnout, g_attnout);
    cudaGetSymbolAddress((void**)&ln,      g_ln);
    cudaGetSymbolAddress((void**)&kvpart,  g_kvpart);
    cudaGetSymbolAddress((void**)&kspart,  g_kspart);
    cudaGetSymbolAddress((void**)&kv,      g_kv);
    cudaGetSymbolAddress((void**)&ksum,    g_ksum);
    cudaGetSymbolAddress((void**)&Wqkvp,   g_Wqkvp);
    cudaGetSymbolAddress((void**)&Woutp,   g_Woutp);
    cudaGetSymbolAddress((void**)&W1p,     g_W1p);
    cudaGetSymbolAddress((void**)&W2p,     g_W2p);

    // weight convert: fp32 -> fp16
    {
        int n4;
        n4 = L_*3*INNER_*D_ / 4; wconv_kernel<<<(n4+255)/256, 256>>>(Wqkv, Wqkvp, n4);
        n4 = L_*D_*INNER_   / 4; wconv_kernel<<<(n4+255)/256, 256>>>(Wout, Woutp, n4);
        n4 = L_*FF_*D_      / 4; wconv_kernel<<<(n4+255)/256, 256>>>(W1,   W1p,   n4);
        n4 = L_*D_*FF_      / 4; wconv_kernel<<<(n4+255)/256, 256>>>(W2,   W2p,   n4);
    }

    embed_kernel<<<M_, 256>>>(tokens, tok_emb, pos_emb, x);

    for (int l = 0; l < L_; l++) {
        const __half* Wqkv_l = Wqkvp + (size_t)l * 3 * INNER_ * D_;
        const __half* Wout_l = Woutp + (size_t)l * D_ * INNER_;
        const float* bout_l = bout + (size_t)l * D_;
        const float* ln1g_l = ln1g + (size_t)l * D_;
        const float* ln1b_l = ln1b + (size_t)l * D_;
        const float* ln2g_l = ln2g + (size_t)l * D_;
        const float* ln2b_l = ln2b + (size_t)l * D_;
        const __half* W1_l  = W1p  + (size_t)l * FF_ * D_;
        const float* b1_l   = b1   + (size_t)l * FF_;
        const __half* W2_l  = W2p  + (size_t)l * D_ * FF_;
        const float* b2_l   = b2   + (size_t)l * D_;
        const float* rf_l   = rf   + (size_t)l * H_ * DH_ * R_;

        // --- attention block ---
        ln_kernel<<<M_, 256>>>(x, ln1g_l, ln1b_l, ln);
        gemm_fp16<0, false><<<dim3(3 * INNER_ / 128, M_ / 128), 256>>>(
            ln, Wqkv_l, qkv, M_, 3 * INNER_, D_, nullptr, nullptr);
        kvsum_kernel<<<dim3(B_ * H_, NCHUNK_), 256>>>(qkv, rf_l, kvpart, kspart);
        kvreduce_kernel<<<B_ * H_, 256>>>(kvpart, kspart, kv, ksum);
        attnout_kernel<<<dim3(B_ * H_, N_ / 128), 256>>>(qkv, rf_l, kv, ksum, attnout);
        gemm_fp16<3, false><<<dim3(D_ / 128, M_ / 128), 256>>>(
            attnout, Wout_l, x, M_, D_, INNER_, bout_l, x);

        // --- FFN block ---
        ln_kernel<<<M_, 256>>>(x, ln2g_l, ln2b_l, ln);
        gemm_fp16<2, true><<<dim3(FF_ / 128, M_ / 128), 256>>>(
            ln, W1_l, ff1, M_, FF_, D_, b1_l, nullptr);
        gemm_fp16<3, false><<<dim3(D_ / 128, M_ / 128), 256>>>(
            ff1, W2_l, x, M_, D_, FF_, b2_l, x);
    }
}

// round 14
// speedup vs baseline: 1.2063x; 1.0413x over previous
#include <cuda_runtime.h>
#include <cuda_fp16.h>
#include <math.h>
#include <stdint.h>

// ---------------- problem constants ----------------
#define B_   2
#define N_   4096
#define D_   1024
#define H_   16
#define DH_  64
#define R_   64
#define L_   6
#define FF_  4096
#define INNER_ 1024
#define M_   (B_*N_)        // 8192 rows
#define EPS_ 1e-5f
#define STAB_ 1e-6f
#define NCHUNK_ 32          // kv-sum chunks per (b,h)

// ---------------- scratch (static device globals; allowed) ----------------
__device__ __align__(16) __half g_qkv[M_ * 3 * INNER_];    // [phi_q | phi_k | v], half
__device__ __align__(16) __half g_ff1[M_ * FF_];
__device__ __align__(16) __half g_attnout[M_ * INNER_];
__device__ __align__(16) __half g_ln[M_ * D_];
__device__ __align__(16) float  g_kvpart[B_*H_*NCHUNK_*R_*DH_];
__device__ __align__(16) float  g_kspart[B_*H_*NCHUNK_*R_];
__device__ __align__(16) float  g_kv[B_*H_*R_*DH_];
__device__ __align__(16) float  g_ksum[B_*H_*R_];
// fp16 weights: g_Wqkvp holds combined [Wphi_q | Wphi_k | Wv]
__device__ __align__(16) __half g_Wqkvp[L_*3*INNER_*D_];
__device__ __align__(16) __half g_Woutp[L_*D_*INNER_];
__device__ __align__(16) __half g_W1p  [L_*FF_*D_];
__device__ __align__(16) __half g_W2p  [L_*D_*FF_];

// ---------------- helpers ----------------
__device__ __forceinline__ uint32_t smem_u32(const void* p) {
    uint32_t a;
    asm("{ .reg .u64 t; cvta.to.shared.u64 t, %1; cvt.u32.u64 %0, t; }" : "=r"(a) : "l"(p));
    return a;
}
__device__ __forceinline__ void cp16(uint32_t s, const void* g) {
    asm volatile("cp.async.cg.shared.global [%0], [%1], 16;\n" :: "r"(s), "l"(g));
}
#define LDSM_X4(r, addr) \
    asm volatile("ldmatrix.sync.aligned.m8n8.x4.shared.b16 {%0,%1,%2,%3}, [%4];" \
        : "=r"((r)[0]), "=r"((r)[1]), "=r"((r)[2]), "=r"((r)[3]) : "r"(addr))

// ---------------- FP16 tensor-core GEMM, 128x128 tile, k-chunk 32 -----------
// C[M,Nc] = A[M,K] @ Bw[Nc,K]^T  (+ epilogue)
// EPI: 0=none, 1=relu for col<relu_lim, 2=bias+GELU, 3=bias+residual(fp32).
#define KC    32
#define RSTR  40
#define STAGEB (128 * RSTR * 2)

template<int EPI, bool OUTH>
__global__ __launch_bounds__(256) void gemm_fp16(
    const __half* __restrict__ A, const __half* __restrict__ Bw,
    void* __restrict__ Cv, int M, int Nc, int K,
    const float* __restrict__ bias, const float* __restrict__ resid, int relu_lim)
{
    __shared__ __align__(16) __half sh[2][2][128 * RSTR];
    const uint32_t sbase = smem_u32(&sh[0][0][0]);

    const int tid  = threadIdx.x;
    const int bm0  = blockIdx.y * 128;
    const int bn0  = blockIdx.x * 128;
    const int warp = tid >> 5;
    const int lane = tid & 31;
    const int wm   = warp >> 2;
    const int wn   = warp & 3;
    const int g8   = lane >> 2;
    const int qid  = lane & 3;

    float c[4][4][4];
    #pragma unroll
    for (int mi = 0; mi < 4; mi++)
        #pragma unroll
        for (int ni = 0; ni < 4; ni++)
            #pragma unroll
            for (int j = 0; j < 4; j++) c[mi][ni][j] = 0.0f;

    const int nIter = K / KC;

    auto load_stage = [&](int it, int buf) {
        const int k0 = it * KC;
        uint32_t sA = sbase + buf * 2 * STAGEB;
        uint32_t sB = sA + STAGEB;
        #pragma unroll
        for (int i = 0; i < 2; i++) {
            int f = i * 256 + tid;
            int row = f >> 2, seg = f & 3;
            cp16(sA + (row * RSTR + seg * 8) * 2,
                 &A[(size_t)(bm0 + row) * K + k0 + seg * 8]);
        }
        #pragma unroll
        for (int i = 0; i < 2; i++) {
            int f = i * 256 + tid;
            int row = f >> 2, seg = f & 3;
            cp16(sB + (row * RSTR + seg * 8) * 2,
                 &Bw[(size_t)(bn0 + row) * K + k0 + seg * 8]);
        }
        asm volatile("cp.async.commit_group;\n" ::: "memory");
    };

    load_stage(0, 0);

    for (int it = 0; it < nIter; it++) {
        int buf = it & 1;
        if (it + 1 < nIter) {
            load_stage(it + 1, buf ^ 1);
            asm volatile("cp.async.wait_group 1;\n" ::: "memory");
        } else {
            asm volatile("cp.async.wait_group 0;\n" ::: "memory");
        }
        __syncthreads();

        uint32_t sA = sbase + buf * 2 * STAGEB;
        uint32_t sB = sA + STAGEB;

        #pragma unroll
        for (int ks = 0; ks < KC; ks += 16) {
            uint32_t af[4][4];
            #pragma unroll
            for (int mi = 0; mi < 4; mi++) {
                int m0 = wm * 64 + mi * 16;
                uint32_t addr = sA + (((m0 + (lane & 15)) * RSTR) + ks + ((lane >> 4) << 3)) * 2;
                LDSM_X4(af[mi], addr);
            }
            uint32_t bf[2][4];
            #pragma unroll
            for (int nb = 0; nb < 2; nb++) {
                int n0 = wn * 32 + nb * 16;
                uint32_t addr = sB + (((n0 + (lane & 7) + ((lane >> 4) << 3)) * RSTR)
                                      + ks + (((lane >> 3) & 1) << 3)) * 2;
                LDSM_X4(bf[nb], addr);
            }
            #pragma unroll
            for (int mi = 0; mi < 4; mi++)
                #pragma unroll
                for (int ni = 0; ni < 4; ni++) {
                    uint32_t b0 = bf[ni >> 1][(ni & 1) * 2];
                    uint32_t b1 = bf[ni >> 1][(ni & 1) * 2 + 1];
                    asm volatile(
                        "mma.sync.aligned.m16n8k16.row.col.f32.f16.f16.f32 "
                        "{%0,%1,%2,%3}, {%4,%5,%6,%7}, {%8,%9}, {%0,%1,%2,%3};\n"
                        : "+f"(c[mi][ni][0]), "+f"(c[mi][ni][1]),
                          "+f"(c[mi][ni][2]), "+f"(c[mi][ni][3])
                        : "r"(af[mi][0]), "r"(af[mi][1]), "r"(af[mi][2]), "r"(af[mi][3]),
                          "r"(b0), "r"(b1));
                }
        }
        __syncthreads();
    }

    // ---- epilogue ----
    #pragma unroll
    for (int mi = 0; mi < 4; mi++) {
        int row0 = bm0 + wm * 64 + mi * 16 + g8;
        int row1 = row0 + 8;
        #pragma unroll
        for (int ni = 0; ni < 4; ni++) {
            int col = bn0 + wn * 32 + ni * 8 + qid * 2;
            float o0 = c[mi][ni][0], o1 = c[mi][ni][1];
            float o2 = c[mi][ni][2], o3 = c[mi][ni][3];
            if (EPI == 1) {
                if (col < relu_lim) {
                    o0 = fmaxf(o0, 0.0f); o1 = fmaxf(o1, 0.0f);
                    o2 = fmaxf(o2, 0.0f); o3 = fmaxf(o3, 0.0f);
                }
            }
            if (EPI >= 2) {
                float b0 = bias[col], b1 = bias[col + 1];
                o0 += b0; o1 += b1; o2 += b0; o3 += b1;
            }
            if (EPI == 2) {
                o0 = 0.5f * o0 * (1.0f + erff(o0 * 0.70710678118654752f));
                o1 = 0.5f * o1 * (1.0f + erff(o1 * 0.70710678118654752f));
                o2 = 0.5f * o2 * (1.0f + erff(o2 * 0.70710678118654752f));
                o3 = 0.5f * o3 * (1.0f + erff(o3 * 0.70710678118654752f));
            }
            if (EPI == 3) {
                float2 r0 = *(const float2*)&resid[(size_t)row0 * Nc + col];
                float2 r1 = *(const float2*)&resid[(size_t)row1 * Nc + col];
                o0 += r0.x; o1 += r0.y; o2 += r1.x; o3 += r1.y;
            }
            if (OUTH) {
                __half* C = (__half*)Cv;
                *(__half2*)&C[(size_t)row0 * Nc + col] = __floats2half2_rn(o0, o1);
                *(__half2*)&C[(size_t)row1 * Nc + col] = __floats2half2_rn(o2, o3);
            } else {
                float* C = (float*)Cv;
                *(float2*)&C[(size_t)row0 * Nc + col] = make_float2(o0, o1);
                *(float2*)&C[(size_t)row1 * Nc + col] = make_float2(o2, o3);
            }
        }
    }
}

// ---------------- weight convert: fp32 -> fp16 ----------------
__global__ __launch_bounds__(256) void wconv_kernel(
    const float* __restrict__ in, __half* __restrict__ out, int n4)
{
    int i = blockIdx.x * 256 + threadIdx.x;
    if (i >= n4) return;
    float4 v = *(const float4*)&in[(size_t)i * 4];
    *(__half2*)&out[(size_t)i * 4]     = __floats2half2_rn(v.x, v.y);
    *(__half2*)&out[(size_t)i * 4 + 2] = __floats2half2_rn(v.z, v.w);
}

// ---------------- combined phi weights: Wphi[c,(h,r)] = sum_d W[(h,d),c]*rf[h,d,r]
// one block per (l, qk, h); output rows (qk*INNER + h*R + r), fp16
__global__ __launch_bounds__(256) void wcomb_kernel(
    const float* __restrict__ Wqkv, const float* __restrict__ rf,
    __half* __restrict__ out)
{
    __shared__ float rfs[64 * 64];     // [d][r]
    __shared__ float wt[64][64];       // [d][c-tile]
    int blk = blockIdx.x;              // 0..191
    int l = blk >> 5, rest = blk & 31;
    int qk = rest >> 4, h = rest & 15;
    int tid = threadIdx.x;

    const float* W   = Wqkv + ((size_t)l * 3 * INNER_ + qk * INNER_ + h * DH_) * D_;
    const float* rfh = rf + ((size_t)(l * H_ + h)) * DH_ * R_;
    __half* o = out + (size_t)l * 3 * INNER_ * D_ + (size_t)(qk * INNER_ + h * R_) * D_;

    #pragma unroll
    for (int i = 0; i < 16; i++) rfs[tid + i * 256] = rfh[tid + i * 256];
    __syncthreads();

    int r  = tid >> 2;
    int j0 = (tid & 3) << 4;
    for (int ct = 0; ct < 16; ct++) {
        #pragma unroll
        for (int i = 0; i < 16; i++) {
            int f = tid + i * 256;
            int d = f >> 6, cc = f & 63;
            wt[d][cc] = W[(size_t)d * D_ + ct * 64 + cc];
        }
        __syncthreads();
        float acc[16];
        #pragma unroll
        for (int j = 0; j < 16; j++) acc[j] = 0.0f;
        for (int d = 0; d < 64; d++) {
            float p = rfs[d * 64 + r];
            #pragma unroll
            for (int j = 0; j < 16; j++) acc[j] = fmaf(p, wt[d][j0 + j], acc[j]);
        }
        #pragma unroll
        for (int j = 0; j < 16; j += 2)
            *(__half2*)&o[(size_t)r * D_ + ct * 64 + j0 + j] =
                __floats2half2_rn(acc[j], acc[j + 1]);
        __syncthreads();
    }
}

// ---------------- embedding ----------------
__global__ __launch_bounds__(256) void embed_kernel(
    const int* __restrict__ tokens, const float* __restrict__ te,
    const float* __restrict__ pe, float* __restrict__ x)
{
    int row = blockIdx.x;
    int tid = threadIdx.x;
    int n = row & (N_ - 1);
    int tok = tokens[row];
    float4 a = *(const float4*)&te[(size_t)tok * D_ + tid * 4];
    float4 p = *(const float4*)&pe[(size_t)n * D_ + tid * 4];
    a.x += p.x; a.y += p.y; a.z += p.z; a.w += p.w;
    *(float4*)&x[(size_t)row * D_ + tid * 4] = a;
}

// ---------------- fused LayerNorm (stats + apply -> fp16) -------------------
__global__ __launch_bounds__(256) void ln_kernel(
    const float* __restrict__ x, const float* __restrict__ lng,
    const float* __restrict__ lnb, __half* __restrict__ h)
{
    __shared__ float red[256];
    int row = blockIdx.x, tid = threadIdx.x;
    float4 v = *(const float4*)&x[(size_t)row * D_ + tid * 4];
    red[tid] = v.x + v.y + v.z + v.w; __syncthreads();
    #pragma unroll
    for (int o = 128; o > 0; o >>= 1) { if (tid < o) red[tid] += red[tid + o]; __syncthreads(); }
    float mu = red[0] * (1.0f / D_);
    __syncthreads();
    float dx = v.x - mu, dy = v.y - mu, dz = v.z - mu, dw = v.w - mu;
    red[tid] = dx*dx + dy*dy + dz*dz + dw*dw; __syncthreads();
    #pragma unroll
    for (int o = 128; o > 0; o >>= 1) { if (tid < o) red[tid] += red[tid + o]; __syncthreads(); }
    float rs = rsqrtf(red[0] * (1.0f / D_) + EPS_);
    float4 gg = *(const float4*)&lng[tid * 4];
    float4 bb = *(const float4*)&lnb[tid * 4];
    __half* hr = h + (size_t)row * D_ + tid * 4;
    *(__half2*)&hr[0] = __floats2half2_rn(dx * rs * gg.x + bb.x, dy * rs * gg.y + bb.y);
    *(__half2*)&hr[2] = __floats2half2_rn(dz * rs * gg.z + bb.z, dw * rs * gg.w + bb.w);
}

// ---------------- kv-sum (round-13 structure, phi pre-computed) -------------
__global__ __launch_bounds__(256) void kvsum_kernel(
    const __half* __restrict__ qkvh,
    float* __restrict__ kvpart, float* __restrict__ kspart)
{
    __shared__ float vsm[8][64];
    __shared__ float phism[8][64];
    int tid = threadIdx.x;
    int bh = blockIdx.x;
    int b = bh >> 4, h = bh & 15;
    int chunk = blockIdx.y;            // 0..31, 128 rows each

    int prow = tid >> 6, pr = tid & 63;
    float acc[16];
    #pragma unroll
    for (int j = 0; j < 16; j++) acc[j] = 0.0f;
    int my_r  = tid >> 2;
    int my_d0 = (tid & 3) << 4;
    float kslocal = 0.0f;
    int nbase = chunk * 128;

    for (int gidx = 0; gidx < 16; gidx++) {
        int n0 = nbase + gidx * 8 + prow;
        size_t base0 = ((size_t)(b * N_ + n0)) * (3 * INNER_) + h * DH_;
        size_t base1 = base0 + (size_t)4 * (3 * INNER_);
        float p0 = __half2float(qkvh[base0 + INNER_ + pr]);
        float p1 = __half2float(qkvh[base1 + INNER_ + pr]);
        phism[prow    ][pr] = p0;
        phism[prow + 4][pr] = p1;
        vsm[prow    ][pr] = __half2float(qkvh[base0 + 2 * INNER_ + pr]);
        vsm[prow + 4][pr] = __half2float(qkvh[base1 + 2 * INNER_ + pr]);
        kslocal += p0 + p1;
        __syncthreads();
        #pragma unroll
        for (int rr = 0; rr < 8; rr++) {
            float p = phism[rr][my_r];
            float4 v0 = *(const float4*)&vsm[rr][my_d0];
            float4 v1 = *(const float4*)&vsm[rr][my_d0 + 4];
            float4 v2 = *(const float4*)&vsm[rr][my_d0 + 8];
            float4 v3 = *(const float4*)&vsm[rr][my_d0 + 12];
            acc[0]  = fmaf(p, v0.x, acc[0]);  acc[1]  = fmaf(p, v0.y, acc[1]);
            acc[2]  = fmaf(p, v0.z, acc[2]);  acc[3]  = fmaf(p, v0.w, acc[3]);
            acc[4]  = fmaf(p, v1.x, acc[4]);  acc[5]  = fmaf(p, v1.y, acc[5]);
            acc[6]  = fmaf(p, v1.z, acc[6]);  acc[7]  = fmaf(p, v1.w, acc[7]);
            acc[8]  = fmaf(p, v2.x, acc[8]);  acc[9]  = fmaf(p, v2.y, acc[9]);
            acc[10] = fmaf(p, v2.z, acc[10]); acc[11] = fmaf(p, v2.w, acc[11]);
            acc[12] = fmaf(p, v3.x, acc[12]); acc[13] = fmaf(p, v3.y, acc[13]);
            acc[14] = fmaf(p, v3.z, acc[14]); acc[15] = fmaf(p, v3.w, acc[15]);
        }
        __syncthreads();
    }

    float* kvp = kvpart + ((size_t)(bh * NCHUNK_ + chunk)) * (R_ * DH_);
    #pragma unroll
    for (int j = 0; j < 16; j++) kvp[my_r * 64 + my_d0 + j] = acc[j];

    phism[prow][pr] = kslocal;
    __syncthreads();
    if (tid < 64) {
        float s = phism[0][tid] + phism[1][tid] + phism[2][tid] + phism[3][tid];
        kspart[(bh * NCHUNK_ + chunk) * R_ + tid] = s;
    }
}

__global__ __launch_bounds__(256) void kvreduce_kernel(
    const float* __restrict__ kvpart, const float* __restrict__ kspart,
    float* __restrict__ kv, float* __restrict__ ks)
{
    int bh = blockIdx.x, tid = threadIdx.x;
    for (int i = tid; i < R_ * DH_; i += 256) {
        float s = 0.0f;
        #pragma unroll
        for (int c = 0; c < NCHUNK_; c++)
            s += kvpart[((size_t)(bh * NCHUNK_ + c)) * (R_ * DH_) + i];
        kv[(size_t)bh * (R_ * DH_) + i] = s;
    }
    if (tid < 64) {
        float s = 0.0f;
        #pragma unroll
        for (int c = 0; c < NCHUNK_; c++) s += kspart[(bh * NCHUNK_ + c) * R_ + tid];
        ks[bh * R_ + tid] = s;
    }
}

// ---------------- attention out (round-13 structure, phi pre-computed) ------
__global__ __launch_bounds__(256) void attnout_kernel(
    const __half* __restrict__ qkvh,
    const float* __restrict__ kv, const float* __restrict__ ksum,
    __half* __restrict__ out)
{
    __shared__ float kvT[64 * 68];
    __shared__ float kssm[R_];
    __shared__ float phism[8][64];
    int tid = threadIdx.x;
    int bh = blockIdx.x;
    int b = bh >> 4, h = bh & 15;
    int tile = blockIdx.y;

    int prow = tid >> 6, pr = tid & 63;
    const float* kvg = kv + (size_t)bh * (R_ * DH_);
    for (int i = tid; i < R_ * DH_; i += 256) {
        int r = i >> 6, d = i & 63;
        kvT[d * 68 + r] = kvg[i];
    }
    if (tid < 64) kssm[tid] = ksum[bh * R_ + tid];
    __syncthreads();

    int nbase = tile * 128;
    for (int gidx = 0; gidx < 16; gidx++) {
        int n0 = nbase + gidx * 8 + prow;
        size_t base0 = ((size_t)(b * N_ + n0)) * (3 * INNER_) + h * DH_;
        size_t base1 = base0 + (size_t)4 * (3 * INNER_);
        phism[prow    ][pr] = __half2float(qkvh[base0 + pr]);
        phism[prow + 4][pr] = __half2float(qkvh[base1 + pr]);
        __syncthreads();
        float a0 = 0.0f, a1 = 0.0f, z0 = 0.0f, z1 = 0.0f;
        #pragma unroll
        for (int rc = 0; rc < 16; rc++) {
            float4 p0 = *(const float4*)&phism[prow    ][rc * 4];
            float4 p1 = *(const float4*)&phism[prow + 4][rc * 4];
            float4 kk = *(const float4*)&kvT[pr * 68 + rc * 4];
            float4 ss = *(const float4*)&kssm[rc * 4];
            a0 = fmaf(p0.x, kk.x, a0); a0 = fmaf(p0.y, kk.y, a0);
            a0 = fmaf(p0.z, kk.z, a0); a0 = fmaf(p0.w, kk.w, a0);
            z0 = fmaf(p0.x, ss.x, z0); z0 = fmaf(p0.y, ss.y, z0);
            z0 = fmaf(p0.z, ss.z, z0); z0 = fmaf(p0.w, ss.w, z0);
            a1 = fmaf(p1.x, kk.x, a1); a1 = fmaf(p1.y, kk.y, a1);
            a1 = fmaf(p1.z, kk.z, a1); a1 = fmaf(p1.w, kk.w, a1);
            z1 = fmaf(p1.x, ss.x, z1); z1 = fmaf(p1.y, ss.y, z1);
            z1 = fmaf(p1.z, ss.z, z1); z1 = fmaf(p1.w, ss.w, z1);
        }
        out[((size_t)(b * N_ + n0    )) * INNER_ + h * DH_ + pr] = __float2half_rn(a0 / (z0 + STAB_));
        out[((size_t)(b * N_ + n0 + 4)) * INNER_ + h * DH_ + pr] = __float2half_rn(a1 / (z1 + STAB_));
        __syncthreads();
    }
}

// ---------------- host driver ----------------
extern "C" void kernel_launch(void* const* d_in, const int* in_sizes, int n_in,
                              void* d_out, int out_size)
{
    const int*   tokens  = (const int*)  d_in[0];
    const float* tok_emb = (const float*)d_in[1];
    const float* pos_emb = (const float*)d_in[2];
    const float* Wqkv    = (const float*)d_in[3];
    const float* Wout    = (const float*)d_in[4];
    const float* bout    = (const float*)d_in[5];
    const float* ln1g    = (const float*)d_in[6];
    const float* ln1b    = (const float*)d_in[7];
    const float* ln2g    = (const float*)d_in[8];
    const float* ln2b    = (const float*)d_in[9];
    const float* W1      = (const float*)d_in[10];
    const float* b1      = (const float*)d_in[11];
    const float* W2      = (const float*)d_in[12];
    const float* b2      = (const float*)d_in[13];
    const float* rf      = (const float*)d_in[14];
    float* x = (float*)d_out;

    float *kvpart, *kspart, *kv, *ksum;
    __half *qkv, *ff1, *attnout, *ln, *Wqkvp, *Woutp, *W1p, *W2p;
    cudaGetSymbolAddress((void**)&qkv,     g_qkv);
    cudaGetSymbolAddress((void**)&ff1,     g_ff1);
    cudaGetSymbolAddress((void**)&attnout, g_attnout);
    cudaGetSymbolAddress((void**)&ln,      g_ln);
    cudaGetSymbolAddress((void**)&kvpart,  g_kvpart);
    cudaGetSymbolAddress((void**)&kspart,  g_kspart);
    cudaGetSymbolAddress((void**)&kv,      g_kv);
    cudaGetSymbolAddress((void**)&ksum,    g_ksum);
    cudaGetSymbolAddress((void**)&Wqkvp,   g_Wqkvp);
    cudaGetSymbolAddress((void**)&Woutp,   g_Woutp);
    cudaGetSymbolAddress((void**)&W1p,     g_W1p);
    cudaGetSymbolAddress((void**)&W2p,     g_W2p);

    // weight prep: combined phi weights (q,k) + fp16 conversions (v + rest)
    wcomb_kernel<<<L_ * 2 * H_, 256>>>(Wqkv, rf, Wqkvp);
    for (int l = 0; l < L_; l++) {
        int n4 = INNER_ * D_ / 4;
        wconv_kernel<<<(n4 + 255) / 256, 256>>>(
            Wqkv  + (size_t)l * 3 * INNER_ * D_ + 2 * (size_t)INNER_ * D_,
            Wqkvp + (size_t)l * 3 * INNER_ * D_ + 2 * (size_t)INNER_ * D_, n4);
    }
    {
        int n4;
        n4 = L_*D_*INNER_ / 4; wconv_kernel<<<(n4+255)/256, 256>>>(Wout, Woutp, n4);
        n4 = L_*FF_*D_    / 4; wconv_kernel<<<(n4+255)/256, 256>>>(W1,   W1p,   n4);
        n4 = L_*D_*FF_    / 4; wconv_kernel<<<(n4+255)/256, 256>>>(W2,   W2p,   n4);
    }

    embed_kernel<<<M_, 256>>>(tokens, tok_emb, pos_emb, x);

    for (int l = 0; l < L_; l++) {
        const __half* Wqkv_l = Wqkvp + (size_t)l * 3 * INNER_ * D_;
        const __half* Wout_l = Woutp + (size_t)l * D_ * INNER_;
        const float* bout_l = bout + (size_t)l * D_;
        const float* ln1g_l = ln1g + (size_t)l * D_;
        const float* ln1b_l = ln1b + (size_t)l * D_;
        const float* ln2g_l = ln2g + (size_t)l * D_;
        const float* ln2b_l = ln2b + (size_t)l * D_;
        const __half* W1_l  = W1p  + (size_t)l * FF_ * D_;
        const float* b1_l   = b1   + (size_t)l * FF_;
        const __half* W2_l  = W2p  + (size_t)l * D_ * FF_;
        const float* b2_l   = b2   + (size_t)l * D_;

        // --- attention block ---
        ln_kernel<<<M_, 256>>>(x, ln1g_l, ln1b_l, ln);
        gemm_fp16<1, true><<<dim3(3 * INNER_ / 128, M_ / 128), 256>>>(
            ln, Wqkv_l, qkv, M_, 3 * INNER_, D_, nullptr, nullptr, 2 * INNER_);
        kvsum_kernel<<<dim3(B_ * H_, NCHUNK_), 256>>>(qkv, kvpart, kspart);
        kvreduce_kernel<<<B_ * H_, 256>>>(kvpart, kspart, kv, ksum);
        attnout_kernel<<<dim3(B_ * H_, N_ / 128), 256>>>(qkv, kv, ksum, attnout);
        gemm_fp16<3, false><<<dim3(D_ / 128, M_ / 128), 256>>>(
            attnout, Wout_l, x, M_, D_, INNER_, bout_l, x, 0);

        // --- FFN block ---
        ln_kernel<<<M_, 256>>>(x, ln2g_l, ln2b_l, ln);
        gemm_fp16<2, true><<<dim3(FF_ / 128, M_ / 128), 256>>>(
            ln, W1_l, ff1, M_, FF_, D_, b1_l, nullptr, 0);
        gemm_fp16<3, false><<<dim3(D_ / 128, M_ / 128), 256>>>(
            ff1, W2_l, x, M_, D_, FF_, b2_l, x, 0);
    }
}